// round 2
// baseline (speedup 1.0000x reference)
#include <cuda_runtime.h>

#define S_LEN 2048
#define B_SZ  2
#define DM    1024
#define NH    16
#define DK    64

// Scratch (allocation-free rule: __device__ globals)
__device__ float g_Q[(long)B_SZ * S_LEN * DM];   // 16 MB
__device__ float g_K[(long)B_SZ * S_LEN * DM];   // 16 MB
__device__ float g_V[(long)B_SZ * S_LEN * DM];   // 16 MB
__device__ float g_H[(long)B_SZ * S_LEN * DM];   // 16 MB (concat head outputs)
__device__ float g_S[(long)B_SZ * S_LEN * S_LEN];// 33.5 MB (per-head scores/attn)

// ---------------------------------------------------------------------------
// NT SGEMM: C[m,n] = alpha * sum_k A[m,k] * B[n,k]
// A: (M,K) row-major lda ; B: (N,K) row-major ldb ; C: (M,N) row-major ldc
// BM=BN=128, BK=16, 256 threads, 8x8 per-thread tile. Batched via blockIdx.z.
// All dims assumed multiples of tile sizes (true for every call here).
// ---------------------------------------------------------------------------
__global__ __launch_bounds__(256) void sgemm_nt(
    const float* __restrict__ A, const float* __restrict__ B, float* __restrict__ C,
    int M, int N, int K, int lda, int ldb, int ldc,
    long sA, long sB, long sC, float alpha)
{
    const int BM = 128, BN = 128, BK = 16;
    __shared__ float As[BK][BM + 4];
    __shared__ float Bs[BK][BN + 4];

    A += (long)blockIdx.z * sA;
    B += (long)blockIdx.z * sB;
    C += (long)blockIdx.z * sC;

    const int bm = blockIdx.y * BM;
    const int bn = blockIdx.x * BN;
    const int tid = threadIdx.x;
    const int tx = tid & 15;        // n-tile coord (16 x 8 cols)
    const int ty = tid >> 4;        // m-tile coord (16 x 8 rows)

    const int lr = tid >> 2;        // 0..63 load row
    const int lc = (tid & 3) * 4;   // 0,4,8,12 load col (float4)

    float acc[8][8];
    #pragma unroll
    for (int i = 0; i < 8; i++)
        #pragma unroll
        for (int j = 0; j < 8; j++) acc[i][j] = 0.f;

    for (int kk = 0; kk < K; kk += BK) {
        #pragma unroll
        for (int i = 0; i < 2; i++) {
            int r = lr + i * 64;
            float4 v = *reinterpret_cast<const float4*>(&A[(long)(bm + r) * lda + kk + lc]);
            As[lc + 0][r] = v.x; As[lc + 1][r] = v.y;
            As[lc + 2][r] = v.z; As[lc + 3][r] = v.w;
        }
        #pragma unroll
        for (int i = 0; i < 2; i++) {
            int r = lr + i * 64;
            float4 v = *reinterpret_cast<const float4*>(&B[(long)(bn + r) * ldb + kk + lc]);
            Bs[lc + 0][r] = v.x; Bs[lc + 1][r] = v.y;
            Bs[lc + 2][r] = v.z; Bs[lc + 3][r] = v.w;
        }
        __syncthreads();

        #pragma unroll
        for (int k = 0; k < BK; k++) {
            float4 a0 = *reinterpret_cast<float4*>(&As[k][ty * 8]);
            float4 a1 = *reinterpret_cast<float4*>(&As[k][ty * 8 + 4]);
            float4 b0 = *reinterpret_cast<float4*>(&Bs[k][tx * 8]);
            float4 b1 = *reinterpret_cast<float4*>(&Bs[k][tx * 8 + 4]);
            float a[8] = {a0.x, a0.y, a0.z, a0.w, a1.x, a1.y, a1.z, a1.w};
            float b[8] = {b0.x, b0.y, b0.z, b0.w, b1.x, b1.y, b1.z, b1.w};
            #pragma unroll
            for (int i = 0; i < 8; i++)
                #pragma unroll
                for (int j = 0; j < 8; j++)
                    acc[i][j] += a[i] * b[j];
        }
        __syncthreads();
    }

    #pragma unroll
    for (int i = 0; i < 8; i++) {
        long r = (long)(bm + ty * 8 + i) * ldc + bn + tx * 8;
        float4 o0 = make_float4(acc[i][0] * alpha, acc[i][1] * alpha,
                                acc[i][2] * alpha, acc[i][3] * alpha);
        float4 o1 = make_float4(acc[i][4] * alpha, acc[i][5] * alpha,
                                acc[i][6] * alpha, acc[i][7] * alpha);
        *reinterpret_cast<float4*>(&C[r])     = o0;
        *reinterpret_cast<float4*>(&C[r + 4]) = o1;
    }
}

// ---------------------------------------------------------------------------
// NN SGEMM: C[m,n] = sum_k A[m,k] * B[k,n]     (PV: M=2048, N=64, K=2048)
// BM=128, BN=64, BK=16, 256 threads, 8x4 per-thread tile.
// ---------------------------------------------------------------------------
__global__ __launch_bounds__(256) void sgemm_nn(
    const float* __restrict__ A, const float* __restrict__ B, float* __restrict__ C,
    int M, int N, int K, int lda, int ldb, int ldc,
    long sA, long sB, long sC)
{
    const int BM = 128, BN = 64, BK = 16;
    __shared__ float As[BK][BM + 4];
    __shared__ float Bs[BK][BN];

    A += (long)blockIdx.z * sA;
    B += (long)blockIdx.z * sB;
    C += (long)blockIdx.z * sC;

    const int bm = blockIdx.y * BM;
    const int bn = blockIdx.x * BN;
    const int tid = threadIdx.x;
    const int tx = tid & 15;        // n coord: 16 x 4
    const int ty = tid >> 4;        // m coord: 16 x 8

    const int lr = tid >> 2;
    const int lc = (tid & 3) * 4;
    const int br = tid >> 4;        // B tile row 0..15
    const int bc = (tid & 15) * 4;  // B tile col float4

    float acc[8][4];
    #pragma unroll
    for (int i = 0; i < 8; i++)
        #pragma unroll
        for (int j = 0; j < 4; j++) acc[i][j] = 0.f;

    for (int kk = 0; kk < K; kk += BK) {
        #pragma unroll
        for (int i = 0; i < 2; i++) {
            int r = lr + i * 64;
            float4 v = *reinterpret_cast<const float4*>(&A[(long)(bm + r) * lda + kk + lc]);
            As[lc + 0][r] = v.x; As[lc + 1][r] = v.y;
            As[lc + 2][r] = v.z; As[lc + 3][r] = v.w;
        }
        {
            float4 v = *reinterpret_cast<const float4*>(&B[(long)(kk + br) * ldb + bn + bc]);
            *reinterpret_cast<float4*>(&Bs[br][bc]) = v;
        }
        __syncthreads();

        #pragma unroll
        for (int k = 0; k < BK; k++) {
            float4 a0 = *reinterpret_cast<float4*>(&As[k][ty * 8]);
            float4 a1 = *reinterpret_cast<float4*>(&As[k][ty * 8 + 4]);
            float4 b0 = *reinterpret_cast<float4*>(&Bs[k][tx * 4]);
            float a[8] = {a0.x, a0.y, a0.z, a0.w, a1.x, a1.y, a1.z, a1.w};
            float b[4] = {b0.x, b0.y, b0.z, b0.w};
            #pragma unroll
            for (int i = 0; i < 8; i++)
                #pragma unroll
                for (int j = 0; j < 4; j++)
                    acc[i][j] += a[i] * b[j];
        }
        __syncthreads();
    }

    #pragma unroll
    for (int i = 0; i < 8; i++) {
        long r = (long)(bm + ty * 8 + i) * ldc + bn + tx * 4;
        *reinterpret_cast<float4*>(&C[r]) =
            make_float4(acc[i][0], acc[i][1], acc[i][2], acc[i][3]);
    }
}

// ---------------------------------------------------------------------------
// Row softmax (in place on g_S) + accumulate mean over heads into attn_weights.
// One block per row (256 threads x 8 elems). first!=0 -> store, else add.
// ---------------------------------------------------------------------------
__global__ __launch_bounds__(256) void softmax_mean_kernel(
    float* __restrict__ Sb, float* __restrict__ AW, int first)
{
    __shared__ float red[8];
    const long base = ((long)blockIdx.y * S_LEN + blockIdx.x) * S_LEN;
    float* row = Sb + base;
    float* aw  = AW + base;
    const int tid = threadIdx.x;

    float4 x0 = *reinterpret_cast<float4*>(&row[tid * 8]);
    float4 x1 = *reinterpret_cast<float4*>(&row[tid * 8 + 4]);
    float v[8] = {x0.x, x0.y, x0.z, x0.w, x1.x, x1.y, x1.z, x1.w};

    float m = v[0];
    #pragma unroll
    for (int i = 1; i < 8; i++) m = fmaxf(m, v[i]);
    #pragma unroll
    for (int o = 16; o > 0; o >>= 1) m = fmaxf(m, __shfl_xor_sync(0xffffffffu, m, o));
    if ((tid & 31) == 0) red[tid >> 5] = m;
    __syncthreads();
    m = red[0];
    #pragma unroll
    for (int i = 1; i < 8; i++) m = fmaxf(m, red[i]);
    __syncthreads();

    float s = 0.f;
    #pragma unroll
    for (int i = 0; i < 8; i++) { v[i] = __expf(v[i] - m); s += v[i]; }
    #pragma unroll
    for (int o = 16; o > 0; o >>= 1) s += __shfl_xor_sync(0xffffffffu, s, o);
    if ((tid & 31) == 0) red[tid >> 5] = s;
    __syncthreads();
    s = 0.f;
    #pragma unroll
    for (int i = 0; i < 8; i++) s += red[i];

    const float inv = 1.f / s;
    #pragma unroll
    for (int i = 0; i < 8; i++) v[i] *= inv;

    *reinterpret_cast<float4*>(&row[tid * 8])     = make_float4(v[0], v[1], v[2], v[3]);
    *reinterpret_cast<float4*>(&row[tid * 8 + 4]) = make_float4(v[4], v[5], v[6], v[7]);

    const float sc = 1.0f / (float)NH;
    if (first) {
        *reinterpret_cast<float4*>(&aw[tid * 8]) =
            make_float4(v[0] * sc, v[1] * sc, v[2] * sc, v[3] * sc);
        *reinterpret_cast<float4*>(&aw[tid * 8 + 4]) =
            make_float4(v[4] * sc, v[5] * sc, v[6] * sc, v[7] * sc);
    } else {
        float4 a0 = *reinterpret_cast<float4*>(&aw[tid * 8]);
        float4 a1 = *reinterpret_cast<float4*>(&aw[tid * 8 + 4]);
        a0.x += v[0] * sc; a0.y += v[1] * sc; a0.z += v[2] * sc; a0.w += v[3] * sc;
        a1.x += v[4] * sc; a1.y += v[5] * sc; a1.z += v[6] * sc; a1.w += v[7] * sc;
        *reinterpret_cast<float4*>(&aw[tid * 8])     = a0;
        *reinterpret_cast<float4*>(&aw[tid * 8 + 4]) = a1;
    }
}

// ---------------------------------------------------------------------------
extern "C" void kernel_launch(void* const* d_in, const int* in_sizes, int n_in,
                              void* d_out, int out_size)
{
    const float* q  = (const float*)d_in[0];
    const float* k  = (const float*)d_in[1];
    const float* v  = (const float*)d_in[2];
    const float* Wq = (const float*)d_in[3];
    const float* Wk = (const float*)d_in[4];
    const float* Wv = (const float*)d_in[5];
    const float* Wo = (const float*)d_in[6];

    float* out  = (float*)d_out;                       // (B, S, DM)
    float* attw = out + (long)B_SZ * S_LEN * DM;       // (B, S, S)

    float *Qb, *Kb, *Vb, *Hb, *Sb;
    cudaGetSymbolAddress((void**)&Qb, g_Q);
    cudaGetSymbolAddress((void**)&Kb, g_K);
    cudaGetSymbolAddress((void**)&Vb, g_V);
    cudaGetSymbolAddress((void**)&Hb, g_H);
    cudaGetSymbolAddress((void**)&Sb, g_S);

    const int MS = B_SZ * S_LEN;   // 4096
    const long sBH = (long)S_LEN * DM;     // batch stride in Q/K/V/H
    const long sSS = (long)S_LEN * S_LEN;  // batch stride in scores

    // 1) Projections: X @ W^T  (4096 x 1024 x 1024)
    {
        dim3 g(DM / 128, MS / 128, 1);
        sgemm_nt<<<g, 256>>>(q, Wq, Qb, MS, DM, DM, DM, DM, DM, 0, 0, 0, 1.f);
        sgemm_nt<<<g, 256>>>(k, Wk, Kb, MS, DM, DM, DM, DM, DM, 0, 0, 0, 1.f);
        sgemm_nt<<<g, 256>>>(v, Wv, Vb, MS, DM, DM, DM, DM, DM, 0, 0, 0, 1.f);
    }

    // 2) Per-head: scores -> softmax (+mean accumulate) -> P@V
    for (int h = 0; h < NH; h++) {
        // scores[b,q,kq] = (1/8) * sum_d Q[b,q,h,d] * K[b,kq,h,d]
        dim3 gs(S_LEN / 128, S_LEN / 128, B_SZ);
        sgemm_nt<<<gs, 256>>>(Qb + h * DK, Kb + h * DK, Sb,
                              S_LEN, S_LEN, DK, DM, DM, S_LEN,
                              sBH, sBH, sSS, 0.125f);

        dim3 gm(S_LEN, B_SZ, 1);
        softmax_mean_kernel<<<gm, 256>>>(Sb, attw, h == 0 ? 1 : 0);

        // head_out[b,q,h,d] = sum_kq P[b,q,kq] * V[b,kq,h,d]
        dim3 gv(DK / 64, S_LEN / 128, B_SZ);
        sgemm_nn<<<gv, 256>>>(Sb, Vb + h * DK, Hb + h * DK,
                              S_LEN, DK, S_LEN, S_LEN, DM, DM,
                              sSS, sBH, sBH);
    }

    // 3) Output projection: H @ Wo^T
    {
        dim3 g(DM / 128, MS / 128, 1);
        sgemm_nt<<<g, 256>>>(Hb, Wo, out, MS, DM, DM, DM, DM, DM, 0, 0, 0, 1.f);
    }
}

// round 7
// speedup vs baseline: 2.2883x; 2.2883x over previous
#include <cuda_runtime.h>

#define S_LEN 2048
#define B_SZ  2
#define DM    1024
#define NH    16
#define DK    64

// Scratch (allocation-free rule: __device__ globals)
__device__ float g_Q[(long)B_SZ * S_LEN * DM];                 // 16 MB
__device__ float g_K[(long)B_SZ * S_LEN * DM];                 // 16 MB
__device__ float g_V[(long)B_SZ * S_LEN * DM];                 // 16 MB
__device__ float g_H[(long)B_SZ * S_LEN * DM];                 // 16 MB
__device__ float g_S[(long)B_SZ * NH * S_LEN * S_LEN];         // 536 MB: [b][h][q][k]

// ---------------------------------------------------------------------------
// NT SGEMM, double-buffered smem: C[m,n] = alpha * sum_k A[m,k]*B[n,k]
// A,B K-contiguous row-major. 256 thr, BM=BN=128, BK=16, 8x8/thread.
// blockIdx.z: z0 = z&1 (batch), z1 = z>>1 (head); offset z0*s?0 + z1*s?1.
// K must be a multiple of 16 (true for all calls here).
// ---------------------------------------------------------------------------
__global__ __launch_bounds__(256, 2) void sgemm_nt(
    const float* __restrict__ A, const float* __restrict__ B, float* __restrict__ C,
    int K, int lda, int ldb, int ldc,
    long sA0, long sA1, long sB0, long sB1, long sC0, long sC1,
    float alpha)
{
    const int BM = 128, BN = 128, BK = 16;
    __shared__ float As[2][BK][BM + 4];
    __shared__ float Bs[2][BK][BN + 4];

    const int z0 = blockIdx.z & 1, z1 = blockIdx.z >> 1;
    A += z0 * sA0 + z1 * sA1;
    B += z0 * sB0 + z1 * sB1;
    C += z0 * sC0 + z1 * sC1;

    const int bm = blockIdx.y * BM;
    const int bn = blockIdx.x * BN;
    const int tid = threadIdx.x;
    const int tx = tid & 15;
    const int ty = tid >> 4;
    const int lr = tid >> 2;
    const int lc = (tid & 3) * 4;

    const float* Ap0 = &A[(long)(bm + lr) * lda + lc];
    const float* Ap1 = &A[(long)(bm + lr + 64) * lda + lc];
    const float* Bp0 = &B[(long)(bn + lr) * ldb + lc];
    const float* Bp1 = &B[(long)(bn + lr + 64) * ldb + lc];

    float acc[8][8];
    #pragma unroll
    for (int i = 0; i < 8; i++)
        #pragma unroll
        for (int j = 0; j < 8; j++) acc[i][j] = 0.f;

    const int T = K / BK;

    // prologue: tile 0 -> buf 0
    {
        float4 a0 = *reinterpret_cast<const float4*>(Ap0);
        float4 a1 = *reinterpret_cast<const float4*>(Ap1);
        float4 b0 = *reinterpret_cast<const float4*>(Bp0);
        float4 b1 = *reinterpret_cast<const float4*>(Bp1);
        As[0][lc+0][lr] = a0.x; As[0][lc+1][lr] = a0.y; As[0][lc+2][lr] = a0.z; As[0][lc+3][lr] = a0.w;
        As[0][lc+0][lr+64] = a1.x; As[0][lc+1][lr+64] = a1.y; As[0][lc+2][lr+64] = a1.z; As[0][lc+3][lr+64] = a1.w;
        Bs[0][lc+0][lr] = b0.x; Bs[0][lc+1][lr] = b0.y; Bs[0][lc+2][lr] = b0.z; Bs[0][lc+3][lr] = b0.w;
        Bs[0][lc+0][lr+64] = b1.x; Bs[0][lc+1][lr+64] = b1.y; Bs[0][lc+2][lr+64] = b1.z; Bs[0][lc+3][lr+64] = b1.w;
    }
    __syncthreads();

    for (int t = 0; t < T; t++) {
        const int cur = t & 1;
        float4 a0, a1, b0, b1;
        const bool more = (t + 1 < T);
        if (more) {
            const int kk = (t + 1) * BK;
            a0 = *reinterpret_cast<const float4*>(Ap0 + kk);
            a1 = *reinterpret_cast<const float4*>(Ap1 + kk);
            b0 = *reinterpret_cast<const float4*>(Bp0 + kk);
            b1 = *reinterpret_cast<const float4*>(Bp1 + kk);
        }

        #pragma unroll
        for (int k = 0; k < BK; k++) {
            float4 fa0 = *reinterpret_cast<float4*>(&As[cur][k][ty * 8]);
            float4 fa1 = *reinterpret_cast<float4*>(&As[cur][k][ty * 8 + 4]);
            float4 fb0 = *reinterpret_cast<float4*>(&Bs[cur][k][tx * 8]);
            float4 fb1 = *reinterpret_cast<float4*>(&Bs[cur][k][tx * 8 + 4]);
            float a[8] = {fa0.x, fa0.y, fa0.z, fa0.w, fa1.x, fa1.y, fa1.z, fa1.w};
            float b[8] = {fb0.x, fb0.y, fb0.z, fb0.w, fb1.x, fb1.y, fb1.z, fb1.w};
            #pragma unroll
            for (int i = 0; i < 8; i++)
                #pragma unroll
                for (int j = 0; j < 8; j++)
                    acc[i][j] += a[i] * b[j];
        }

        if (more) {
            const int nxt = cur ^ 1;
            As[nxt][lc+0][lr] = a0.x; As[nxt][lc+1][lr] = a0.y; As[nxt][lc+2][lr] = a0.z; As[nxt][lc+3][lr] = a0.w;
            As[nxt][lc+0][lr+64] = a1.x; As[nxt][lc+1][lr+64] = a1.y; As[nxt][lc+2][lr+64] = a1.z; As[nxt][lc+3][lr+64] = a1.w;
            Bs[nxt][lc+0][lr] = b0.x; Bs[nxt][lc+1][lr] = b0.y; Bs[nxt][lc+2][lr] = b0.z; Bs[nxt][lc+3][lr] = b0.w;
            Bs[nxt][lc+0][lr+64] = b1.x; Bs[nxt][lc+1][lr+64] = b1.y; Bs[nxt][lc+2][lr+64] = b1.z; Bs[nxt][lc+3][lr+64] = b1.w;
            __syncthreads();
        }
    }

    #pragma unroll
    for (int i = 0; i < 8; i++) {
        long r = (long)(bm + ty * 8 + i) * ldc + bn + tx * 8;
        *reinterpret_cast<float4*>(&C[r]) =
            make_float4(acc[i][0]*alpha, acc[i][1]*alpha, acc[i][2]*alpha, acc[i][3]*alpha);
        *reinterpret_cast<float4*>(&C[r + 4]) =
            make_float4(acc[i][4]*alpha, acc[i][5]*alpha, acc[i][6]*alpha, acc[i][7]*alpha);
    }
}

// ---------------------------------------------------------------------------
// NN SGEMM, double-buffered: C[m,n] = sum_k A[m,k]*B[k,n]
// BM=128, BN=64, BK=16, 256 thr, 8x4/thread. Same z decomposition.
// ---------------------------------------------------------------------------
__global__ __launch_bounds__(256, 2) void sgemm_nn(
    const float* __restrict__ A, const float* __restrict__ B, float* __restrict__ C,
    int K, int lda, int ldb, int ldc,
    long sA0, long sA1, long sB0, long sB1, long sC0, long sC1)
{
    const int BM = 128, BN = 64, BK = 16;
    __shared__ float As[2][BK][BM + 4];
    __shared__ float Bs[2][BK][BN];

    const int z0 = blockIdx.z & 1, z1 = blockIdx.z >> 1;
    A += z0 * sA0 + z1 * sA1;
    B += z0 * sB0 + z1 * sB1;
    C += z0 * sC0 + z1 * sC1;

    const int bm = blockIdx.y * BM;
    const int bn = blockIdx.x * BN;
    const int tid = threadIdx.x;
    const int tx = tid & 15;
    const int ty = tid >> 4;
    const int lr = tid >> 2;
    const int lc = (tid & 3) * 4;
    const int br = tid >> 4;
    const int bc = (tid & 15) * 4;

    const float* Ap0 = &A[(long)(bm + lr) * lda + lc];
    const float* Ap1 = &A[(long)(bm + lr + 64) * lda + lc];
    const float* Bp  = &B[(long)br * ldb + bn + bc];

    float acc[8][4];
    #pragma unroll
    for (int i = 0; i < 8; i++)
        #pragma unroll
        for (int j = 0; j < 4; j++) acc[i][j] = 0.f;

    const int T = K / BK;

    {
        float4 a0 = *reinterpret_cast<const float4*>(Ap0);
        float4 a1 = *reinterpret_cast<const float4*>(Ap1);
        float4 bv = *reinterpret_cast<const float4*>(Bp);
        As[0][lc+0][lr] = a0.x; As[0][lc+1][lr] = a0.y; As[0][lc+2][lr] = a0.z; As[0][lc+3][lr] = a0.w;
        As[0][lc+0][lr+64] = a1.x; As[0][lc+1][lr+64] = a1.y; As[0][lc+2][lr+64] = a1.z; As[0][lc+3][lr+64] = a1.w;
        *reinterpret_cast<float4*>(&Bs[0][br][bc]) = bv;
    }
    __syncthreads();

    for (int t = 0; t < T; t++) {
        const int cur = t & 1;
        float4 a0, a1, bv;
        const bool more = (t + 1 < T);
        if (more) {
            const int kk = (t + 1) * BK;
            a0 = *reinterpret_cast<const float4*>(Ap0 + kk);
            a1 = *reinterpret_cast<const float4*>(Ap1 + kk);
            bv = *reinterpret_cast<const float4*>(Bp + (long)kk * ldb);
        }

        #pragma unroll
        for (int k = 0; k < BK; k++) {
            float4 fa0 = *reinterpret_cast<float4*>(&As[cur][k][ty * 8]);
            float4 fa1 = *reinterpret_cast<float4*>(&As[cur][k][ty * 8 + 4]);
            float4 fb0 = *reinterpret_cast<float4*>(&Bs[cur][k][tx * 4]);
            float a[8] = {fa0.x, fa0.y, fa0.z, fa0.w, fa1.x, fa1.y, fa1.z, fa1.w};
            float b[4] = {fb0.x, fb0.y, fb0.z, fb0.w};
            #pragma unroll
            for (int i = 0; i < 8; i++)
                #pragma unroll
                for (int j = 0; j < 4; j++)
                    acc[i][j] += a[i] * b[j];
        }

        if (more) {
            const int nxt = cur ^ 1;
            As[nxt][lc+0][lr] = a0.x; As[nxt][lc+1][lr] = a0.y; As[nxt][lc+2][lr] = a0.z; As[nxt][lc+3][lr] = a0.w;
            As[nxt][lc+0][lr+64] = a1.x; As[nxt][lc+1][lr+64] = a1.y; As[nxt][lc+2][lr+64] = a1.z; As[nxt][lc+3][lr+64] = a1.w;
            *reinterpret_cast<float4*>(&Bs[nxt][br][bc]) = bv;
            __syncthreads();
        }
    }

    #pragma unroll
    for (int i = 0; i < 8; i++) {
        long r = (long)(bm + ty * 8 + i) * ldc + bn + tx * 4;
        *reinterpret_cast<float4*>(&C[r]) =
            make_float4(acc[i][0], acc[i][1], acc[i][2], acc[i][3]);
    }
}

// ---------------------------------------------------------------------------
// In-place row softmax over g_S, batched over all (b,h,q) rows.
// grid = (S_LEN, B*NH), 256 threads x 8 elements.
// ---------------------------------------------------------------------------
__global__ __launch_bounds__(256) void softmax_kernel(float* __restrict__ Sb)
{
    __shared__ float red[8];
    float* row = Sb + ((long)blockIdx.y * S_LEN + blockIdx.x) * S_LEN;
    const int tid = threadIdx.x;

    float4 x0 = *reinterpret_cast<float4*>(&row[tid * 8]);
    float4 x1 = *reinterpret_cast<float4*>(&row[tid * 8 + 4]);
    float v[8] = {x0.x, x0.y, x0.z, x0.w, x1.x, x1.y, x1.z, x1.w};

    float m = v[0];
    #pragma unroll
    for (int i = 1; i < 8; i++) m = fmaxf(m, v[i]);
    #pragma unroll
    for (int o = 16; o > 0; o >>= 1) m = fmaxf(m, __shfl_xor_sync(0xffffffffu, m, o));
    if ((tid & 31) == 0) red[tid >> 5] = m;
    __syncthreads();
    m = red[0];
    #pragma unroll
    for (int i = 1; i < 8; i++) m = fmaxf(m, red[i]);
    __syncthreads();

    float s = 0.f;
    #pragma unroll
    for (int i = 0; i < 8; i++) { v[i] = __expf(v[i] - m); s += v[i]; }
    #pragma unroll
    for (int o = 16; o > 0; o >>= 1) s += __shfl_xor_sync(0xffffffffu, s, o);
    if ((tid & 31) == 0) red[tid >> 5] = s;
    __syncthreads();
    s = 0.f;
    #pragma unroll
    for (int i = 0; i < 8; i++) s += red[i];

    const float inv = 1.f / s;
    #pragma unroll
    for (int i = 0; i < 8; i++) v[i] *= inv;

    *reinterpret_cast<float4*>(&row[tid * 8])     = make_float4(v[0], v[1], v[2], v[3]);
    *reinterpret_cast<float4*>(&row[tid * 8 + 4]) = make_float4(v[4], v[5], v[6], v[7]);
}

// ---------------------------------------------------------------------------
// attn_weights[b,q,k] = mean over h of P[b,h,q,k]. Coalesced float4 pass.
// grid = (S*S/2048, B), 512 threads.
// ---------------------------------------------------------------------------
__global__ __launch_bounds__(512) void mean_heads_kernel(
    const float* __restrict__ Sb, float* __restrict__ AW)
{
    const long SS = (long)S_LEN * S_LEN;
    const long idx = ((long)blockIdx.x * 512 + threadIdx.x) * 4;
    const float* p = Sb + (long)blockIdx.y * NH * SS + idx;

    float4 a = make_float4(0.f, 0.f, 0.f, 0.f);
    #pragma unroll
    for (int h = 0; h < NH; h++) {
        float4 v = *reinterpret_cast<const float4*>(p + (long)h * SS);
        a.x += v.x; a.y += v.y; a.z += v.z; a.w += v.w;
    }
    const float sc = 1.0f / (float)NH;
    *reinterpret_cast<float4*>(AW + (long)blockIdx.y * SS + idx) =
        make_float4(a.x * sc, a.y * sc, a.z * sc, a.w * sc);
}

// ---------------------------------------------------------------------------
extern "C" void kernel_launch(void* const* d_in, const int* in_sizes, int n_in,
                              void* d_out, int out_size)
{
    const float* q  = (const float*)d_in[0];
    const float* k  = (const float*)d_in[1];
    const float* v  = (const float*)d_in[2];
    const float* Wq = (const float*)d_in[3];
    const float* Wk = (const float*)d_in[4];
    const float* Wv = (const float*)d_in[5];
    const float* Wo = (const float*)d_in[6];

    float* out  = (float*)d_out;                       // (B, S, DM)
    float* attw = out + (long)B_SZ * S_LEN * DM;       // (B, S, S)

    float *Qb, *Kb, *Vb, *Hb, *Sb;
    cudaGetSymbolAddress((void**)&Qb, g_Q);
    cudaGetSymbolAddress((void**)&Kb, g_K);
    cudaGetSymbolAddress((void**)&Vb, g_V);
    cudaGetSymbolAddress((void**)&Hb, g_H);
    cudaGetSymbolAddress((void**)&Sb, g_S);

    const int MS = B_SZ * S_LEN;             // 4096
    const long sBH = (long)S_LEN * DM;       // batch stride in Q/K/V/H
    const long SS  = (long)S_LEN * S_LEN;    // per (b,h) score plane

    // 1) Projections: X @ W^T  (4096 x 1024 x 1024)
    {
        dim3 g(DM / 128, MS / 128, 1);
        sgemm_nt<<<g, 256>>>(q, Wq, Qb, DM, DM, DM, DM, 0,0, 0,0, 0,0, 1.f);
        sgemm_nt<<<g, 256>>>(k, Wk, Kb, DM, DM, DM, DM, 0,0, 0,0, 0,0, 1.f);
        sgemm_nt<<<g, 256>>>(v, Wv, Vb, DM, DM, DM, DM, 0,0, 0,0, 0,0, 1.f);
    }

    // 2) Scores for ALL (b,h): z = (h<<1)|b
    {
        dim3 g(S_LEN / 128, S_LEN / 128, B_SZ * NH);
        sgemm_nt<<<g, 256>>>(Qb, Kb, Sb, DK, DM, DM, S_LEN,
                             sBH, DK,           // A: batch, head strides
                             sBH, DK,           // B
                             NH * SS, SS,       // C: [b][h][q][k]
                             0.125f);
    }

    // 3) Softmax in place over all 65536 rows
    {
        dim3 g(S_LEN, B_SZ * NH, 1);
        softmax_kernel<<<g, 256>>>(Sb);
    }

    // 4) Mean over heads -> attn_weights
    {
        dim3 g((unsigned)(SS / 2048), B_SZ, 1);
        mean_heads_kernel<<<g, 512>>>(Sb, attw);
    }

    // 5) PV for ALL (b,h): head_out[b,q,h*64+d] = sum_k P[b,h,q,k] * V[b,k,h*64+d]
    {
        dim3 g(DK / 64, S_LEN / 128, B_SZ * NH);
        sgemm_nn<<<g, 256>>>(Sb, Vb, Hb, S_LEN, S_LEN, DM, DM,
                             NH * SS, SS,       // A = P
                             sBH, DK,           // B = V
                             sBH, DK);          // C = H
    }

    // 6) Output projection: H @ Wo^T
    {
        dim3 g(DM / 128, MS / 128, 1);
        sgemm_nt<<<g, 256>>>(Hb, Wo, out, DM, DM, DM, DM, 0,0, 0,0, 0,0, 1.f);
    }
}

// round 9
// speedup vs baseline: 2.4520x; 1.0716x over previous
#include <cuda_runtime.h>

#define S_LEN 2048
#define B_SZ  2
#define DM    1024
#define NH    16
#define DK    64

// Scratch (allocation-free rule: __device__ globals)
__device__ float g_Q[(long)B_SZ * S_LEN * DM];                 // 16 MB
__device__ float g_K[(long)B_SZ * S_LEN * DM];                 // 16 MB
__device__ float g_V[(long)B_SZ * S_LEN * DM];                 // 16 MB
__device__ float g_H[(long)B_SZ * S_LEN * DM];                 // 16 MB
__device__ float g_S[(long)B_SZ * NH * S_LEN * S_LEN];         // 536 MB: [b][h][q][k]

// ---- packed fp32x2 helpers (SASS FFMA2 — only reachable via PTX f32x2) ----
__device__ __forceinline__ void ffma2(unsigned long long& d,
                                      unsigned long long a,
                                      unsigned long long b) {
    asm("fma.rn.f32x2 %0, %1, %2, %0;" : "+l"(d) : "l"(a), "l"(b));
}
__device__ __forceinline__ unsigned long long dup2(float x) {
    unsigned long long r;
    asm("mov.b64 %0, {%1, %1};" : "=l"(r) : "f"(x));
    return r;
}
__device__ __forceinline__ void unpack2(unsigned long long v, float& lo, float& hi) {
    asm("mov.b64 {%0, %1}, %2;" : "=f"(lo), "=f"(hi) : "l"(v));
}

// ---------------------------------------------------------------------------
// NT SGEMM, double-buffered smem, FFMA2 inner loop.
// C[m,n] = alpha * sum_k A[m,k]*B[n,k].  BM=BN=128, BK=16, 256 thr.
// Per thread: 8x8 output, accumulated as 4 row-pairs x 8 cols in f32x2.
// blockIdx.z: z0=z&1 (batch), z1=z>>1 (head).
// ---------------------------------------------------------------------------
__global__ __launch_bounds__(256, 2) void sgemm_nt(
    const float* __restrict__ A, const float* __restrict__ B, float* __restrict__ C,
    int K, int lda, int ldb, int ldc,
    long sA0, long sA1, long sB0, long sB1, long sC0, long sC1,
    float alpha)
{
    const int BM = 128, BN = 128, BK = 16;
    __shared__ float As[2][BK][BM + 4];
    __shared__ float Bs[2][BK][BN + 4];

    const int z0 = blockIdx.z & 1, z1 = blockIdx.z >> 1;
    A += z0 * sA0 + z1 * sA1;
    B += z0 * sB0 + z1 * sB1;
    C += z0 * sC0 + z1 * sC1;

    const int bm = blockIdx.y * BM;
    const int bn = blockIdx.x * BN;
    const int tid = threadIdx.x;
    const int tx = tid & 15;
    const int ty = tid >> 4;
    const int lr = tid >> 2;
    const int lc = (tid & 3) * 4;

    const float* Ap0 = &A[(long)(bm + lr) * lda + lc];
    const float* Ap1 = &A[(long)(bm + lr + 64) * lda + lc];
    const float* Bp0 = &B[(long)(bn + lr) * ldb + lc];
    const float* Bp1 = &B[(long)(bn + lr + 64) * ldb + lc];

    unsigned long long acc[4][8];   // row-pairs (2p,2p+1) x cols j
    #pragma unroll
    for (int p = 0; p < 4; p++)
        #pragma unroll
        for (int j = 0; j < 8; j++) acc[p][j] = 0ull;

    const int T = K / BK;

    {   // prologue: tile 0 -> buf 0
        float4 a0 = *reinterpret_cast<const float4*>(Ap0);
        float4 a1 = *reinterpret_cast<const float4*>(Ap1);
        float4 b0 = *reinterpret_cast<const float4*>(Bp0);
        float4 b1 = *reinterpret_cast<const float4*>(Bp1);
        As[0][lc+0][lr] = a0.x; As[0][lc+1][lr] = a0.y; As[0][lc+2][lr] = a0.z; As[0][lc+3][lr] = a0.w;
        As[0][lc+0][lr+64] = a1.x; As[0][lc+1][lr+64] = a1.y; As[0][lc+2][lr+64] = a1.z; As[0][lc+3][lr+64] = a1.w;
        Bs[0][lc+0][lr] = b0.x; Bs[0][lc+1][lr] = b0.y; Bs[0][lc+2][lr] = b0.z; Bs[0][lc+3][lr] = b0.w;
        Bs[0][lc+0][lr+64] = b1.x; Bs[0][lc+1][lr+64] = b1.y; Bs[0][lc+2][lr+64] = b1.z; Bs[0][lc+3][lr+64] = b1.w;
    }
    __syncthreads();

    for (int t = 0; t < T; t++) {
        const int cur = t & 1;
        float4 a0, a1, b0, b1;
        const bool more = (t + 1 < T);
        if (more) {
            const int kk = (t + 1) * BK;
            a0 = *reinterpret_cast<const float4*>(Ap0 + kk);
            a1 = *reinterpret_cast<const float4*>(Ap1 + kk);
            b0 = *reinterpret_cast<const float4*>(Bp0 + kk);
            b1 = *reinterpret_cast<const float4*>(Bp1 + kk);
        }

        #pragma unroll
        for (int k = 0; k < BK; k++) {
            // A row-pairs: contiguous floats -> load directly as packed f32x2
            ulonglong2 av0 = *reinterpret_cast<const ulonglong2*>(&As[cur][k][ty * 8]);
            ulonglong2 av1 = *reinterpret_cast<const ulonglong2*>(&As[cur][k][ty * 8 + 4]);
            float4 fb0 = *reinterpret_cast<const float4*>(&Bs[cur][k][tx * 8]);
            float4 fb1 = *reinterpret_cast<const float4*>(&Bs[cur][k][tx * 8 + 4]);
            unsigned long long ap[4] = {av0.x, av0.y, av1.x, av1.y};
            unsigned long long bd[8] = {dup2(fb0.x), dup2(fb0.y), dup2(fb0.z), dup2(fb0.w),
                                        dup2(fb1.x), dup2(fb1.y), dup2(fb1.z), dup2(fb1.w)};
            #pragma unroll
            for (int p = 0; p < 4; p++)
                #pragma unroll
                for (int j = 0; j < 8; j++)
                    ffma2(acc[p][j], ap[p], bd[j]);
        }

        if (more) {
            const int nxt = cur ^ 1;
            As[nxt][lc+0][lr] = a0.x; As[nxt][lc+1][lr] = a0.y; As[nxt][lc+2][lr] = a0.z; As[nxt][lc+3][lr] = a0.w;
            As[nxt][lc+0][lr+64] = a1.x; As[nxt][lc+1][lr+64] = a1.y; As[nxt][lc+2][lr+64] = a1.z; As[nxt][lc+3][lr+64] = a1.w;
            Bs[nxt][lc+0][lr] = b0.x; Bs[nxt][lc+1][lr] = b0.y; Bs[nxt][lc+2][lr] = b0.z; Bs[nxt][lc+3][lr] = b0.w;
            Bs[nxt][lc+0][lr+64] = b1.x; Bs[nxt][lc+1][lr+64] = b1.y; Bs[nxt][lc+2][lr+64] = b1.z; Bs[nxt][lc+3][lr+64] = b1.w;
            __syncthreads();
        }
    }

    #pragma unroll
    for (int p = 0; p < 4; p++) {
        float r0[8], r1[8];
        #pragma unroll
        for (int j = 0; j < 8; j++) unpack2(acc[p][j], r0[j], r1[j]);
        long ra = (long)(bm + ty * 8 + 2 * p) * ldc + bn + tx * 8;
        long rb = ra + ldc;
        *reinterpret_cast<float4*>(&C[ra]) =
            make_float4(r0[0]*alpha, r0[1]*alpha, r0[2]*alpha, r0[3]*alpha);
        *reinterpret_cast<float4*>(&C[ra + 4]) =
            make_float4(r0[4]*alpha, r0[5]*alpha, r0[6]*alpha, r0[7]*alpha);
        *reinterpret_cast<float4*>(&C[rb]) =
            make_float4(r1[0]*alpha, r1[1]*alpha, r1[2]*alpha, r1[3]*alpha);
        *reinterpret_cast<float4*>(&C[rb + 4]) =
            make_float4(r1[4]*alpha, r1[5]*alpha, r1[6]*alpha, r1[7]*alpha);
    }
}

// ---------------------------------------------------------------------------
// NN SGEMM, double-buffered, FFMA2: C[m,n] = sum_k A[m,k]*B[k,n]
// BM=128, BN=64, BK=16, 256 thr; 4 row-pairs x 4 cols per thread.
// ---------------------------------------------------------------------------
__global__ __launch_bounds__(256, 2) void sgemm_nn(
    const float* __restrict__ A, const float* __restrict__ B, float* __restrict__ C,
    int K, int lda, int ldb, int ldc,
    long sA0, long sA1, long sB0, long sB1, long sC0, long sC1)
{
    const int BM = 128, BN = 64, BK = 16;
    __shared__ float As[2][BK][BM + 4];
    __shared__ float Bs[2][BK][BN];

    const int z0 = blockIdx.z & 1, z1 = blockIdx.z >> 1;
    A += z0 * sA0 + z1 * sA1;
    B += z0 * sB0 + z1 * sB1;
    C += z0 * sC0 + z1 * sC1;

    const int bm = blockIdx.y * BM;
    const int bn = blockIdx.x * BN;
    const int tid = threadIdx.x;
    const int tx = tid & 15;
    const int ty = tid >> 4;
    const int lr = tid >> 2;
    const int lc = (tid & 3) * 4;
    const int br = tid >> 4;
    const int bc = (tid & 15) * 4;

    const float* Ap0 = &A[(long)(bm + lr) * lda + lc];
    const float* Ap1 = &A[(long)(bm + lr + 64) * lda + lc];
    const float* Bp  = &B[(long)br * ldb + bn + bc];

    unsigned long long acc[4][4];
    #pragma unroll
    for (int p = 0; p < 4; p++)
        #pragma unroll
        for (int j = 0; j < 4; j++) acc[p][j] = 0ull;

    const int T = K / BK;

    {
        float4 a0 = *reinterpret_cast<const float4*>(Ap0);
        float4 a1 = *reinterpret_cast<const float4*>(Ap1);
        float4 bv = *reinterpret_cast<const float4*>(Bp);
        As[0][lc+0][lr] = a0.x; As[0][lc+1][lr] = a0.y; As[0][lc+2][lr] = a0.z; As[0][lc+3][lr] = a0.w;
        As[0][lc+0][lr+64] = a1.x; As[0][lc+1][lr+64] = a1.y; As[0][lc+2][lr+64] = a1.z; As[0][lc+3][lr+64] = a1.w;
        *reinterpret_cast<float4*>(&Bs[0][br][bc]) = bv;
    }
    __syncthreads();

    for (int t = 0; t < T; t++) {
        const int cur = t & 1;
        float4 a0, a1, bv;
        const bool more = (t + 1 < T);
        if (more) {
            const int kk = (t + 1) * BK;
            a0 = *reinterpret_cast<const float4*>(Ap0 + kk);
            a1 = *reinterpret_cast<const float4*>(Ap1 + kk);
            bv = *reinterpret_cast<const float4*>(Bp + (long)kk * ldb);
        }

        #pragma unroll
        for (int k = 0; k < BK; k++) {
            ulonglong2 av0 = *reinterpret_cast<const ulonglong2*>(&As[cur][k][ty * 8]);
            ulonglong2 av1 = *reinterpret_cast<const ulonglong2*>(&As[cur][k][ty * 8 + 4]);
            float4 fb0 = *reinterpret_cast<const float4*>(&Bs[cur][k][tx * 4]);
            unsigned long long ap[4] = {av0.x, av0.y, av1.x, av1.y};
            unsigned long long bd[4] = {dup2(fb0.x), dup2(fb0.y), dup2(fb0.z), dup2(fb0.w)};
            #pragma unroll
            for (int p = 0; p < 4; p++)
                #pragma unroll
                for (int j = 0; j < 4; j++)
                    ffma2(acc[p][j], ap[p], bd[j]);
        }

        if (more) {
            const int nxt = cur ^ 1;
            As[nxt][lc+0][lr] = a0.x; As[nxt][lc+1][lr] = a0.y; As[nxt][lc+2][lr] = a0.z; As[nxt][lc+3][lr] = a0.w;
            As[nxt][lc+0][lr+64] = a1.x; As[nxt][lc+1][lr+64] = a1.y; As[nxt][lc+2][lr+64] = a1.z; As[nxt][lc+3][lr+64] = a1.w;
            *reinterpret_cast<float4*>(&Bs[nxt][br][bc]) = bv;
            __syncthreads();
        }
    }

    #pragma unroll
    for (int p = 0; p < 4; p++) {
        float r0[4], r1[4];
        #pragma unroll
        for (int j = 0; j < 4; j++) unpack2(acc[p][j], r0[j], r1[j]);
        long ra = (long)(bm + ty * 8 + 2 * p) * ldc + bn + tx * 4;
        long rb = ra + ldc;
        *reinterpret_cast<float4*>(&C[ra]) = make_float4(r0[0], r0[1], r0[2], r0[3]);
        *reinterpret_cast<float4*>(&C[rb]) = make_float4(r1[0], r1[1], r1[2], r1[3]);
    }
}

// ---------------------------------------------------------------------------
// Fused softmax (in place) + mean over heads.
// One block per (q, b); iterates all 16 heads for that row, accumulating
// the head-mean in registers, then writes attn_weights once.
// grid = (S_LEN, B_SZ), 256 threads x 8 elements.
// ---------------------------------------------------------------------------
__global__ __launch_bounds__(256) void softmax_mean_all(
    float* __restrict__ Sb, float* __restrict__ AW)
{
    __shared__ float red[8];
    const int b = blockIdx.y, qi = blockIdx.x, tid = threadIdx.x;

    float macc[8] = {0.f, 0.f, 0.f, 0.f, 0.f, 0.f, 0.f, 0.f};
    const float sc = 1.0f / (float)NH;

    #pragma unroll 1
    for (int h = 0; h < NH; h++) {
        float* row = Sb + ((long)((b * NH + h) * S_LEN) + qi) * S_LEN;

        float4 x0 = *reinterpret_cast<float4*>(&row[tid * 8]);
        float4 x1 = *reinterpret_cast<float4*>(&row[tid * 8 + 4]);
        float v[8] = {x0.x, x0.y, x0.z, x0.w, x1.x, x1.y, x1.z, x1.w};

        float m = v[0];
        #pragma unroll
        for (int i = 1; i < 8; i++) m = fmaxf(m, v[i]);
        #pragma unroll
        for (int o = 16; o > 0; o >>= 1) m = fmaxf(m, __shfl_xor_sync(0xffffffffu, m, o));
        if ((tid & 31) == 0) red[tid >> 5] = m;
        __syncthreads();
        m = red[0];
        #pragma unroll
        for (int i = 1; i < 8; i++) m = fmaxf(m, red[i]);
        __syncthreads();

        float s = 0.f;
        #pragma unroll
        for (int i = 0; i < 8; i++) { v[i] = __expf(v[i] - m); s += v[i]; }
        #pragma unroll
        for (int o = 16; o > 0; o >>= 1) s += __shfl_xor_sync(0xffffffffu, s, o);
        if ((tid & 31) == 0) red[tid >> 5] = s;
        __syncthreads();
        s = 0.f;
        #pragma unroll
        for (int i = 0; i < 8; i++) s += red[i];
        __syncthreads();   // red reused next head

        const float inv = 1.f / s;
        #pragma unroll
        for (int i = 0; i < 8; i++) { v[i] *= inv; macc[i] += v[i] * sc; }

        *reinterpret_cast<float4*>(&row[tid * 8])     = make_float4(v[0], v[1], v[2], v[3]);
        *reinterpret_cast<float4*>(&row[tid * 8 + 4]) = make_float4(v[4], v[5], v[6], v[7]);
    }

    float* aw = AW + ((long)b * S_LEN + qi) * S_LEN;
    *reinterpret_cast<float4*>(&aw[tid * 8])     = make_float4(macc[0], macc[1], macc[2], macc[3]);
    *reinterpret_cast<float4*>(&aw[tid * 8 + 4]) = make_float4(macc[4], macc[5], macc[6], macc[7]);
}

// ---------------------------------------------------------------------------
extern "C" void kernel_launch(void* const* d_in, const int* in_sizes, int n_in,
                              void* d_out, int out_size)
{
    const float* q  = (const float*)d_in[0];
    const float* k  = (const float*)d_in[1];
    const float* v  = (const float*)d_in[2];
    const float* Wq = (const float*)d_in[3];
    const float* Wk = (const float*)d_in[4];
    const float* Wv = (const float*)d_in[5];
    const float* Wo = (const float*)d_in[6];

    float* out  = (float*)d_out;                       // (B, S, DM)
    float* attw = out + (long)B_SZ * S_LEN * DM;       // (B, S, S)

    float *Qb, *Kb, *Vb, *Hb, *Sb;
    cudaGetSymbolAddress((void**)&Qb, g_Q);
    cudaGetSymbolAddress((void**)&Kb, g_K);
    cudaGetSymbolAddress((void**)&Vb, g_V);
    cudaGetSymbolAddress((void**)&Hb, g_H);
    cudaGetSymbolAddress((void**)&Sb, g_S);

    const int MS = B_SZ * S_LEN;             // 4096
    const long sBH = (long)S_LEN * DM;       // batch stride in Q/K/V/H
    const long SS  = (long)S_LEN * S_LEN;    // per (b,h) score plane

    // 1) Projections: X @ W^T  (4096 x 1024 x 1024)
    {
        dim3 g(DM / 128, MS / 128, 1);
        sgemm_nt<<<g, 256>>>(q, Wq, Qb, DM, DM, DM, DM, 0,0, 0,0, 0,0, 1.f);
        sgemm_nt<<<g, 256>>>(k, Wk, Kb, DM, DM, DM, DM, 0,0, 0,0, 0,0, 1.f);
        sgemm_nt<<<g, 256>>>(v, Wv, Vb, DM, DM, DM, DM, 0,0, 0,0, 0,0, 1.f);
    }

    // 2) Scores for ALL (b,h): z = (h<<1)|b
    {
        dim3 g(S_LEN / 128, S_LEN / 128, B_SZ * NH);
        sgemm_nt<<<g, 256>>>(Qb, Kb, Sb, DK, DM, DM, S_LEN,
                             sBH, DK, sBH, DK, NH * SS, SS, 0.125f);
    }

    // 3) Fused softmax + mean over heads
    {
        dim3 g(S_LEN, B_SZ, 1);
        softmax_mean_all<<<g, 256>>>(Sb, attw);
    }

    // 4) PV for ALL (b,h): head_out[b,q,h*64+d] = sum_k P[b,h,q,k] * V[b,k,h*64+d]
    {
        dim3 g(DK / 64, S_LEN / 128, B_SZ * NH);
        sgemm_nn<<<g, 256>>>(Sb, Vb, Hb, S_LEN, S_LEN, DM, DM,
                             NH * SS, SS, sBH, DK, sBH, DK);
    }

    // 5) Output projection: H @ Wo^T
    {
        dim3 g(DM / 128, MS / 128, 1);
        sgemm_nt<<<g, 256>>>(Hb, Wo, out, DM, DM, DM, DM, 0,0, 0,0, 0,0, 1.f);
    }
}

// round 11
// speedup vs baseline: 3.4788x; 1.4187x over previous
#include <cuda_runtime.h>
#include <cuda_bf16.h>

#define S_LEN 2048
#define B_SZ  2
#define DM    1024
#define NH    16
#define DK    64

// Scratch (allocation-free rule: __device__ globals)
__device__ float g_Q [(long)B_SZ * S_LEN * DM];                 // 16 MB
__device__ float g_K [(long)B_SZ * S_LEN * DM];                 // 16 MB
__device__ float g_V [(long)B_SZ * S_LEN * DM];                 // 16 MB
__device__ float g_Vt[(long)B_SZ * DM * S_LEN];                 // 16 MB: [b][dm][s]
__device__ float g_H [(long)B_SZ * S_LEN * DM];                 // 16 MB
__device__ float g_S [(long)B_SZ * NH * S_LEN * S_LEN];         // 536 MB: [b][h][q][k]

// ---- bf16 hi/lo split helpers -------------------------------------------
__device__ __forceinline__ void split2(float x, float y, unsigned& hi, unsigned& lo) {
    __nv_bfloat162 h = __floats2bfloat162_rn(x, y);          // .x=low half
    float rx = x - __bfloat162float(h.x);
    float ry = y - __bfloat162float(h.y);
    __nv_bfloat162 l = __floats2bfloat162_rn(rx, ry);
    hi = *reinterpret_cast<unsigned*>(&h);
    lo = *reinterpret_cast<unsigned*>(&l);
}

__device__ __forceinline__ void mma_bf16(float& d0, float& d1, float& d2, float& d3,
                                         unsigned a0, unsigned a1, unsigned a2, unsigned a3,
                                         unsigned b0, unsigned b1) {
    asm volatile(
        "mma.sync.aligned.m16n8k16.row.col.f32.bf16.bf16.f32 "
        "{%0,%1,%2,%3},{%4,%5,%6,%7},{%8,%9},{%0,%1,%2,%3};"
        : "+f"(d0), "+f"(d1), "+f"(d2), "+f"(d3)
        : "r"(a0), "r"(a1), "r"(a2), "r"(a3), "r"(b0), "r"(b1));
}

// ---------------------------------------------------------------------------
// NT GEMM on tensor cores with fp32-accurate bf16 hi/lo split (3 MMAs).
// C[m,n] = alpha * sum_k A[m,k] * B[n,k];  A (M,K) lda, B (N,K) ldb, both
// K-contiguous. BM=128, BN = BN_T (128 or 64), BK=16, 256 threads (8 warps,
// 2m x 4n), warp tile 64 x (BN_T/4). Double-buffered smem, stride-12 u32
// rows (conflict-free fragment loads). blockIdx.z: z0=z&1, z1=z>>1.
// ---------------------------------------------------------------------------
template<int BN_T>
__global__ __launch_bounds__(256, 2) void mma_nt(
    const float* __restrict__ A, const float* __restrict__ B, float* __restrict__ C,
    int K, int lda, int ldb, int ldc,
    long sA0, long sA1, long sB0, long sB1, long sC0, long sC1, float alpha)
{
    const int WN = BN_T / 32;          // n-tiles (of 8) per warp: 4 or 2
    __shared__ unsigned sAh[2][128][12], sAl[2][128][12];
    __shared__ unsigned sBh[2][BN_T][12], sBl[2][BN_T][12];

    const int z0 = blockIdx.z & 1, z1 = blockIdx.z >> 1;
    A += z0 * sA0 + z1 * sA1;
    B += z0 * sB0 + z1 * sB1;
    C += z0 * sC0 + z1 * sC1;

    const int bm = blockIdx.y * 128;
    const int bn = blockIdx.x * BN_T;
    const int tid = threadIdx.x;

    // ---- loaders ----
    const int ar  = tid >> 1;                 // 0..127
    const int ak  = (tid & 1) * 8;            // k offset 0/8
    const int ak2 = (tid & 1) * 4;            // u32 index base
    const float* Ap = &A[(long)(bm + ar) * lda + ak];

    int brr, bk, bk2;
    if (BN_T == 128) { brr = tid >> 1; bk = (tid & 1) * 8; bk2 = (tid & 1) * 4; }
    else             { brr = tid >> 2; bk = (tid & 3) * 4; bk2 = (tid & 3) * 2; }
    const float* Bp = &B[(long)(bn + brr) * ldb + bk];

    // ---- fragment coords ----
    const int w = tid >> 5, lane = tid & 31;
    const int wm = w & 1, wn = w >> 1;
    const int g = lane >> 2, tg = lane & 3;

    float acc[4][WN][4];
    #pragma unroll
    for (int mt = 0; mt < 4; mt++)
        #pragma unroll
        for (int nt = 0; nt < WN; nt++)
            #pragma unroll
            for (int c = 0; c < 4; c++) acc[mt][nt][c] = 0.f;

    const int T = K / 16;

    // prologue -> buffer 0
    {
        float4 v0 = *reinterpret_cast<const float4*>(Ap);
        float4 v1 = *reinterpret_cast<const float4*>(Ap + 4);
        unsigned h, l;
        split2(v0.x, v0.y, h, l); sAh[0][ar][ak2+0] = h; sAl[0][ar][ak2+0] = l;
        split2(v0.z, v0.w, h, l); sAh[0][ar][ak2+1] = h; sAl[0][ar][ak2+1] = l;
        split2(v1.x, v1.y, h, l); sAh[0][ar][ak2+2] = h; sAl[0][ar][ak2+2] = l;
        split2(v1.z, v1.w, h, l); sAh[0][ar][ak2+3] = h; sAl[0][ar][ak2+3] = l;
        if (BN_T == 128) {
            float4 u0 = *reinterpret_cast<const float4*>(Bp);
            float4 u1 = *reinterpret_cast<const float4*>(Bp + 4);
            split2(u0.x, u0.y, h, l); sBh[0][brr][bk2+0] = h; sBl[0][brr][bk2+0] = l;
            split2(u0.z, u0.w, h, l); sBh[0][brr][bk2+1] = h; sBl[0][brr][bk2+1] = l;
            split2(u1.x, u1.y, h, l); sBh[0][brr][bk2+2] = h; sBl[0][brr][bk2+2] = l;
            split2(u1.z, u1.w, h, l); sBh[0][brr][bk2+3] = h; sBl[0][brr][bk2+3] = l;
        } else {
            float4 u0 = *reinterpret_cast<const float4*>(Bp);
            split2(u0.x, u0.y, h, l); sBh[0][brr][bk2+0] = h; sBl[0][brr][bk2+0] = l;
            split2(u0.z, u0.w, h, l); sBh[0][brr][bk2+1] = h; sBl[0][brr][bk2+1] = l;
        }
    }
    __syncthreads();

    for (int t = 0; t < T; t++) {
        const int cur = t & 1;
        const bool more = (t + 1 < T);
        float4 v0, v1, u0, u1;
        if (more) {
            const int kk = (t + 1) * 16;
            v0 = *reinterpret_cast<const float4*>(Ap + kk);
            v1 = *reinterpret_cast<const float4*>(Ap + kk + 4);
            u0 = *reinterpret_cast<const float4*>(Bp + kk);
            if (BN_T == 128) u1 = *reinterpret_cast<const float4*>(Bp + kk + 4);
        }

        // B fragments for this warp (reused across all m-tiles)
        unsigned Bh[WN][2], Bl[WN][2];
        #pragma unroll
        for (int nt = 0; nt < WN; nt++) {
            const int cb = wn * WN * 8 + nt * 8 + g;
            Bh[nt][0] = sBh[cur][cb][tg];     Bh[nt][1] = sBh[cur][cb][tg + 4];
            Bl[nt][0] = sBl[cur][cb][tg];     Bl[nt][1] = sBl[cur][cb][tg + 4];
        }

        #pragma unroll
        for (int mt = 0; mt < 4; mt++) {
            const int ra = wm * 64 + mt * 16 + g;
            unsigned Ah0 = sAh[cur][ra][tg],     Ah1 = sAh[cur][ra + 8][tg];
            unsigned Ah2 = sAh[cur][ra][tg + 4], Ah3 = sAh[cur][ra + 8][tg + 4];
            unsigned Al0 = sAl[cur][ra][tg],     Al1 = sAl[cur][ra + 8][tg];
            unsigned Al2 = sAl[cur][ra][tg + 4], Al3 = sAl[cur][ra + 8][tg + 4];
            #pragma unroll
            for (int nt = 0; nt < WN; nt++) {
                float* d = acc[mt][nt];
                mma_bf16(d[0], d[1], d[2], d[3], Ah0, Ah1, Ah2, Ah3, Bh[nt][0], Bh[nt][1]);
                mma_bf16(d[0], d[1], d[2], d[3], Ah0, Ah1, Ah2, Ah3, Bl[nt][0], Bl[nt][1]);
                mma_bf16(d[0], d[1], d[2], d[3], Al0, Al1, Al2, Al3, Bh[nt][0], Bh[nt][1]);
            }
        }

        if (more) {
            const int nxt = cur ^ 1;
            unsigned h, l;
            split2(v0.x, v0.y, h, l); sAh[nxt][ar][ak2+0] = h; sAl[nxt][ar][ak2+0] = l;
            split2(v0.z, v0.w, h, l); sAh[nxt][ar][ak2+1] = h; sAl[nxt][ar][ak2+1] = l;
            split2(v1.x, v1.y, h, l); sAh[nxt][ar][ak2+2] = h; sAl[nxt][ar][ak2+2] = l;
            split2(v1.z, v1.w, h, l); sAh[nxt][ar][ak2+3] = h; sAl[nxt][ar][ak2+3] = l;
            split2(u0.x, u0.y, h, l); sBh[nxt][brr][bk2+0] = h; sBl[nxt][brr][bk2+0] = l;
            split2(u0.z, u0.w, h, l); sBh[nxt][brr][bk2+1] = h; sBl[nxt][brr][bk2+1] = l;
            if (BN_T == 128) {
                split2(u1.x, u1.y, h, l); sBh[nxt][brr][bk2+2] = h; sBl[nxt][brr][bk2+2] = l;
                split2(u1.z, u1.w, h, l); sBh[nxt][brr][bk2+3] = h; sBl[nxt][brr][bk2+3] = l;
            }
            __syncthreads();
        }
    }

    // epilogue: c0,c1 contiguous (row g), c2,c3 (row g+8)
    #pragma unroll
    for (int mt = 0; mt < 4; mt++)
        #pragma unroll
        for (int nt = 0; nt < WN; nt++) {
            const int row = bm + wm * 64 + mt * 16 + g;
            const int col = bn + wn * WN * 8 + nt * 8 + 2 * tg;
            float* d = acc[mt][nt];
            *reinterpret_cast<float2*>(&C[(long)row * ldc + col]) =
                make_float2(d[0] * alpha, d[1] * alpha);
            *reinterpret_cast<float2*>(&C[(long)(row + 8) * ldc + col]) =
                make_float2(d[2] * alpha, d[3] * alpha);
        }
}

// ---------------------------------------------------------------------------
// V transpose: Vt[b, dm, s] = V[b, s, dm].  32x32 tiles, block (32,8).
// ---------------------------------------------------------------------------
__global__ __launch_bounds__(256) void transpose_v(
    const float* __restrict__ V, float* __restrict__ Vt)
{
    __shared__ float t[32][33];
    const int b = blockIdx.z;
    const int s0 = blockIdx.x * 32, d0 = blockIdx.y * 32;
    const int x = threadIdx.x, y0 = threadIdx.y;

    #pragma unroll
    for (int i = 0; i < 32; i += 8)
        t[y0 + i][x] = V[(long)b * S_LEN * DM + (long)(s0 + y0 + i) * DM + d0 + x];
    __syncthreads();
    #pragma unroll
    for (int i = 0; i < 32; i += 8)
        Vt[(long)b * DM * S_LEN + (long)(d0 + y0 + i) * S_LEN + s0 + x] = t[x][y0 + i];
}

// ---------------------------------------------------------------------------
// Fused softmax (in place) + mean over heads.
// One block per (q, b); iterates 16 heads, accumulates mean in registers.
// grid = (S_LEN, B_SZ), 256 threads x 8 elements.
// ---------------------------------------------------------------------------
__global__ __launch_bounds__(256) void softmax_mean_all(
    float* __restrict__ Sb, float* __restrict__ AW)
{
    __shared__ float red[8];
    const int b = blockIdx.y, qi = blockIdx.x, tid = threadIdx.x;

    float macc[8] = {0.f, 0.f, 0.f, 0.f, 0.f, 0.f, 0.f, 0.f};
    const float sc = 1.0f / (float)NH;

    #pragma unroll 1
    for (int h = 0; h < NH; h++) {
        float* row = Sb + ((long)((b * NH + h) * S_LEN) + qi) * S_LEN;

        float4 x0 = *reinterpret_cast<float4*>(&row[tid * 8]);
        float4 x1 = *reinterpret_cast<float4*>(&row[tid * 8 + 4]);
        float v[8] = {x0.x, x0.y, x0.z, x0.w, x1.x, x1.y, x1.z, x1.w};

        float m = v[0];
        #pragma unroll
        for (int i = 1; i < 8; i++) m = fmaxf(m, v[i]);
        #pragma unroll
        for (int o = 16; o > 0; o >>= 1) m = fmaxf(m, __shfl_xor_sync(0xffffffffu, m, o));
        if ((tid & 31) == 0) red[tid >> 5] = m;
        __syncthreads();
        m = red[0];
        #pragma unroll
        for (int i = 1; i < 8; i++) m = fmaxf(m, red[i]);
        __syncthreads();

        float s = 0.f;
        #pragma unroll
        for (int i = 0; i < 8; i++) { v[i] = __expf(v[i] - m); s += v[i]; }
        #pragma unroll
        for (int o = 16; o > 0; o >>= 1) s += __shfl_xor_sync(0xffffffffu, s, o);
        if ((tid & 31) == 0) red[tid >> 5] = s;
        __syncthreads();
        s = 0.f;
        #pragma unroll
        for (int i = 0; i < 8; i++) s += red[i];
        __syncthreads();   // red reused next head

        const float inv = 1.f / s;
        #pragma unroll
        for (int i = 0; i < 8; i++) { v[i] *= inv; macc[i] += v[i] * sc; }

        *reinterpret_cast<float4*>(&row[tid * 8])     = make_float4(v[0], v[1], v[2], v[3]);
        *reinterpret_cast<float4*>(&row[tid * 8 + 4]) = make_float4(v[4], v[5], v[6], v[7]);
    }

    float* aw = AW + ((long)b * S_LEN + qi) * S_LEN;
    *reinterpret_cast<float4*>(&aw[tid * 8])     = make_float4(macc[0], macc[1], macc[2], macc[3]);
    *reinterpret_cast<float4*>(&aw[tid * 8 + 4]) = make_float4(macc[4], macc[5], macc[6], macc[7]);
}

// ---------------------------------------------------------------------------
extern "C" void kernel_launch(void* const* d_in, const int* in_sizes, int n_in,
                              void* d_out, int out_size)
{
    const float* q  = (const float*)d_in[0];
    const float* k  = (const float*)d_in[1];
    const float* v  = (const float*)d_in[2];
    const float* Wq = (const float*)d_in[3];
    const float* Wk = (const float*)d_in[4];
    const float* Wv = (const float*)d_in[5];
    const float* Wo = (const float*)d_in[6];

    float* out  = (float*)d_out;                       // (B, S, DM)
    float* attw = out + (long)B_SZ * S_LEN * DM;       // (B, S, S)

    float *Qb, *Kb, *Vb, *Vt, *Hb, *Sb;
    cudaGetSymbolAddress((void**)&Qb, g_Q);
    cudaGetSymbolAddress((void**)&Kb, g_K);
    cudaGetSymbolAddress((void**)&Vb, g_V);
    cudaGetSymbolAddress((void**)&Vt, g_Vt);
    cudaGetSymbolAddress((void**)&Hb, g_H);
    cudaGetSymbolAddress((void**)&Sb, g_S);

    const int MS = B_SZ * S_LEN;             // 4096
    const long sBH = (long)S_LEN * DM;       // batch stride in Q/K/V/H
    const long SS  = (long)S_LEN * S_LEN;    // per (b,h) score plane

    // 1) Projections: X @ W^T  (4096 x 1024 x 1024), tensor cores
    {
        dim3 g(DM / 128, MS / 128, 1);
        mma_nt<128><<<g, 256>>>(q, Wq, Qb, DM, DM, DM, DM, 0,0, 0,0, 0,0, 1.f);
        mma_nt<128><<<g, 256>>>(k, Wk, Kb, DM, DM, DM, DM, 0,0, 0,0, 0,0, 1.f);
        mma_nt<128><<<g, 256>>>(v, Wv, Vb, DM, DM, DM, DM, 0,0, 0,0, 0,0, 1.f);
    }

    // 2) Transpose V -> Vt[b, dm, s]
    {
        dim3 g(S_LEN / 32, DM / 32, B_SZ);
        transpose_v<<<g, dim3(32, 8, 1)>>>(Vb, Vt);
    }

    // 3) Scores for ALL (b,h): z = (h<<1)|b
    {
        dim3 g(S_LEN / 128, S_LEN / 128, B_SZ * NH);
        mma_nt<128><<<g, 256>>>(Qb, Kb, Sb, DK, DM, DM, S_LEN,
                                sBH, DK, sBH, DK, NH * SS, SS, 0.125f);
    }

    // 4) Fused softmax + mean over heads
    {
        dim3 g(S_LEN, B_SZ, 1);
        softmax_mean_all<<<g, 256>>>(Sb, attw);
    }

    // 5) PV as NT: head_out[b,q,h*64+d] = sum_k P[b,h,q,k] * Vt[b,h*64+d,k]
    {
        dim3 g(1, S_LEN / 128, B_SZ * NH);
        mma_nt<64><<<g, 256>>>(Sb, Vt, Hb, S_LEN, S_LEN, S_LEN, DM,
                               NH * SS, SS,
                               (long)NH * DK * S_LEN, (long)DK * S_LEN,
                               sBH, DK, 1.f);
    }

    // 6) Output projection: H @ Wo^T
    {
        dim3 g(DM / 128, MS / 128, 1);
        mma_nt<128><<<g, 256>>>(Hb, Wo, out, DM, DM, DM, DM, 0,0, 0,0, 0,0, 1.f);
    }
}

// round 12
// speedup vs baseline: 3.8254x; 1.0996x over previous
#include <cuda_runtime.h>
#include <cuda_bf16.h>

#define S_LEN 2048
#define B_SZ  2
#define DM    1024
#define NH    16
#define DK    64

// Scratch (allocation-free rule: __device__ globals)
__device__ float g_Q [(long)B_SZ * S_LEN * DM];                 // 16 MB
__device__ float g_K [(long)B_SZ * S_LEN * DM];                 // 16 MB
__device__ float g_V [(long)B_SZ * S_LEN * DM];                 // 16 MB
__device__ float g_Vt[(long)B_SZ * DM * S_LEN];                 // 16 MB: [b][dm][s]
__device__ float g_H [(long)B_SZ * S_LEN * DM];                 // 16 MB
__device__ float g_S [(long)B_SZ * NH * S_LEN * S_LEN];         // 536 MB: [b][h][q][k]

// ---- bf16 hi/lo split helpers -------------------------------------------
__device__ __forceinline__ void split2(float x, float y, unsigned& hi, unsigned& lo) {
    __nv_bfloat162 h = __floats2bfloat162_rn(x, y);          // .x=low half
    float rx = x - __bfloat162float(h.x);
    float ry = y - __bfloat162float(h.y);
    __nv_bfloat162 l = __floats2bfloat162_rn(rx, ry);
    hi = *reinterpret_cast<unsigned*>(&h);
    lo = *reinterpret_cast<unsigned*>(&l);
}

__device__ __forceinline__ void mma_bf16(float& d0, float& d1, float& d2, float& d3,
                                         unsigned a0, unsigned a1, unsigned a2, unsigned a3,
                                         unsigned b0, unsigned b1) {
    asm volatile(
        "mma.sync.aligned.m16n8k16.row.col.f32.bf16.bf16.f32 "
        "{%0,%1,%2,%3},{%4,%5,%6,%7},{%8,%9},{%0,%1,%2,%3};"
        : "+f"(d0), "+f"(d1), "+f"(d2), "+f"(d3)
        : "r"(a0), "r"(a1), "r"(a2), "r"(a3), "r"(b0), "r"(b1));
}

__device__ __forceinline__ unsigned sptr(const void* p) {
    return (unsigned)__cvta_generic_to_shared(p);
}
__device__ __forceinline__ void ldm_x4(unsigned& r0, unsigned& r1, unsigned& r2, unsigned& r3,
                                       unsigned addr) {
    asm volatile("ldmatrix.sync.aligned.m8n8.x4.shared.b16 {%0,%1,%2,%3}, [%4];"
                 : "=r"(r0), "=r"(r1), "=r"(r2), "=r"(r3) : "r"(addr));
}
__device__ __forceinline__ void ldm_x2(unsigned& r0, unsigned& r1, unsigned addr) {
    asm volatile("ldmatrix.sync.aligned.m8n8.x2.shared.b16 {%0,%1}, [%2];"
                 : "=r"(r0), "=r"(r1) : "r"(addr));
}

// ---------------------------------------------------------------------------
// NT GEMM on tensor cores, fp32-accurate bf16 hi/lo split (3 MMAs), fragment
// loads via ldmatrix. C[m,n] = alpha * sum_k A[m,k]*B[n,k]; A,B K-contiguous.
// BM=128, BN=BN_T (128/64), BK=16, 256 thr (8 warps 2m x 4n), double-buffered
// smem with stride-12 u32 rows (conflict-free for LDSM: 16B-group = 3r mod 8).
// blockIdx.z: z0=z&1 (batch), z1=z>>1 (head).
// ---------------------------------------------------------------------------
template<int BN_T>
__global__ __launch_bounds__(256, 2) void mma_nt(
    const float* __restrict__ A, const float* __restrict__ B, float* __restrict__ C,
    int K, int lda, int ldb, int ldc,
    long sA0, long sA1, long sB0, long sB1, long sC0, long sC1, float alpha)
{
    const int WN = BN_T / 32;          // n-tiles (of 8) per warp: 4 or 2
    __shared__ unsigned sAh[2][128][12], sAl[2][128][12];
    __shared__ unsigned sBh[2][BN_T][12], sBl[2][BN_T][12];

    const int z0 = blockIdx.z & 1, z1 = blockIdx.z >> 1;
    A += z0 * sA0 + z1 * sA1;
    B += z0 * sB0 + z1 * sB1;
    C += z0 * sC0 + z1 * sC1;

    const int bm = blockIdx.y * 128;
    const int bn = blockIdx.x * BN_T;
    const int tid = threadIdx.x;

    // ---- loaders ----
    const int ar  = tid >> 1;                 // 0..127
    const int ak  = (tid & 1) * 8;            // k offset 0/8
    const int ak2 = (tid & 1) * 4;            // u32 index base
    const float* Ap = &A[(long)(bm + ar) * lda + ak];

    int brr, bk, bk2;
    if (BN_T == 128) { brr = tid >> 1; bk = (tid & 1) * 8; bk2 = (tid & 1) * 4; }
    else             { brr = tid >> 2; bk = (tid & 3) * 4; bk2 = (tid & 3) * 2; }
    const float* Bp = &B[(long)(bn + brr) * ldb + bk];

    // ---- fragment coords ----
    const int w = tid >> 5, lane = tid & 31;
    const int wm = w & 1, wn = w >> 1;
    const int g = lane >> 2, tg = lane & 3;

    // ldmatrix per-lane address components
    const int lmrow = lane & 15;              // A: row within 16-row tile
    const int lmoff = (lane >> 4) * 4;        // A: u32 chunk 0 / 4
    const int lbrow = lane & 7;               // B: row within 8-row tile
    const int lboff = ((lane >> 3) & 1) * 4;  // B: u32 chunk 0 / 4

    float acc[4][WN][4];
    #pragma unroll
    for (int mt = 0; mt < 4; mt++)
        #pragma unroll
        for (int nt = 0; nt < WN; nt++)
            #pragma unroll
            for (int c = 0; c < 4; c++) acc[mt][nt][c] = 0.f;

    const int T = K / 16;

    // prologue -> buffer 0
    {
        float4 v0 = *reinterpret_cast<const float4*>(Ap);
        float4 v1 = *reinterpret_cast<const float4*>(Ap + 4);
        unsigned h, l;
        split2(v0.x, v0.y, h, l); sAh[0][ar][ak2+0] = h; sAl[0][ar][ak2+0] = l;
        split2(v0.z, v0.w, h, l); sAh[0][ar][ak2+1] = h; sAl[0][ar][ak2+1] = l;
        split2(v1.x, v1.y, h, l); sAh[0][ar][ak2+2] = h; sAl[0][ar][ak2+2] = l;
        split2(v1.z, v1.w, h, l); sAh[0][ar][ak2+3] = h; sAl[0][ar][ak2+3] = l;
        if (BN_T == 128) {
            float4 u0 = *reinterpret_cast<const float4*>(Bp);
            float4 u1 = *reinterpret_cast<const float4*>(Bp + 4);
            split2(u0.x, u0.y, h, l); sBh[0][brr][bk2+0] = h; sBl[0][brr][bk2+0] = l;
            split2(u0.z, u0.w, h, l); sBh[0][brr][bk2+1] = h; sBl[0][brr][bk2+1] = l;
            split2(u1.x, u1.y, h, l); sBh[0][brr][bk2+2] = h; sBl[0][brr][bk2+2] = l;
            split2(u1.z, u1.w, h, l); sBh[0][brr][bk2+3] = h; sBl[0][brr][bk2+3] = l;
        } else {
            float4 u0 = *reinterpret_cast<const float4*>(Bp);
            split2(u0.x, u0.y, h, l); sBh[0][brr][bk2+0] = h; sBl[0][brr][bk2+0] = l;
            split2(u0.z, u0.w, h, l); sBh[0][brr][bk2+1] = h; sBl[0][brr][bk2+1] = l;
        }
    }
    __syncthreads();

    for (int t = 0; t < T; t++) {
        const int cur = t & 1;
        const bool more = (t + 1 < T);
        float4 v0, v1, u0, u1;
        if (more) {
            const int kk = (t + 1) * 16;
            v0 = *reinterpret_cast<const float4*>(Ap + kk);
            v1 = *reinterpret_cast<const float4*>(Ap + kk + 4);
            u0 = *reinterpret_cast<const float4*>(Bp + kk);
            if (BN_T == 128) u1 = *reinterpret_cast<const float4*>(Bp + kk + 4);
        }

        // B fragments for this warp (ldmatrix.x2, hi & lo)
        unsigned Bh[WN][2], Bl[WN][2];
        #pragma unroll
        for (int nt = 0; nt < WN; nt++) {
            const int cb = wn * WN * 8 + nt * 8;
            ldm_x2(Bh[nt][0], Bh[nt][1], sptr(&sBh[cur][cb + lbrow][lboff]));
            ldm_x2(Bl[nt][0], Bl[nt][1], sptr(&sBl[cur][cb + lbrow][lboff]));
        }

        #pragma unroll
        for (int mt = 0; mt < 4; mt++) {
            const int ra = wm * 64 + mt * 16;
            unsigned Ah0, Ah1, Ah2, Ah3, Al0, Al1, Al2, Al3;
            ldm_x4(Ah0, Ah1, Ah2, Ah3, sptr(&sAh[cur][ra + lmrow][lmoff]));
            ldm_x4(Al0, Al1, Al2, Al3, sptr(&sAl[cur][ra + lmrow][lmoff]));
            #pragma unroll
            for (int nt = 0; nt < WN; nt++) {
                float* d = acc[mt][nt];
                mma_bf16(d[0], d[1], d[2], d[3], Ah0, Ah1, Ah2, Ah3, Bh[nt][0], Bh[nt][1]);
                mma_bf16(d[0], d[1], d[2], d[3], Ah0, Ah1, Ah2, Ah3, Bl[nt][0], Bl[nt][1]);
                mma_bf16(d[0], d[1], d[2], d[3], Al0, Al1, Al2, Al3, Bh[nt][0], Bh[nt][1]);
            }
        }

        if (more) {
            const int nxt = cur ^ 1;
            unsigned h, l;
            split2(v0.x, v0.y, h, l); sAh[nxt][ar][ak2+0] = h; sAl[nxt][ar][ak2+0] = l;
            split2(v0.z, v0.w, h, l); sAh[nxt][ar][ak2+1] = h; sAl[nxt][ar][ak2+1] = l;
            split2(v1.x, v1.y, h, l); sAh[nxt][ar][ak2+2] = h; sAl[nxt][ar][ak2+2] = l;
            split2(v1.z, v1.w, h, l); sAh[nxt][ar][ak2+3] = h; sAl[nxt][ar][ak2+3] = l;
            split2(u0.x, u0.y, h, l); sBh[nxt][brr][bk2+0] = h; sBl[nxt][brr][bk2+0] = l;
            split2(u0.z, u0.w, h, l); sBh[nxt][brr][bk2+1] = h; sBl[nxt][brr][bk2+1] = l;
            if (BN_T == 128) {
                split2(u1.x, u1.y, h, l); sBh[nxt][brr][bk2+2] = h; sBl[nxt][brr][bk2+2] = l;
                split2(u1.z, u1.w, h, l); sBh[nxt][brr][bk2+3] = h; sBl[nxt][brr][bk2+3] = l;
            }
            __syncthreads();
        }
    }

    // epilogue: c0,c1 contiguous (row g), c2,c3 (row g+8)
    #pragma unroll
    for (int mt = 0; mt < 4; mt++)
        #pragma unroll
        for (int nt = 0; nt < WN; nt++) {
            const int row = bm + wm * 64 + mt * 16 + g;
            const int col = bn + wn * WN * 8 + nt * 8 + 2 * tg;
            float* d = acc[mt][nt];
            *reinterpret_cast<float2*>(&C[(long)row * ldc + col]) =
                make_float2(d[0] * alpha, d[1] * alpha);
            *reinterpret_cast<float2*>(&C[(long)(row + 8) * ldc + col]) =
                make_float2(d[2] * alpha, d[3] * alpha);
        }
}

// ---------------------------------------------------------------------------
// V transpose: Vt[b, dm, s] = V[b, s, dm].  32x32 tiles, block (32,8).
// ---------------------------------------------------------------------------
__global__ __launch_bounds__(256) void transpose_v(
    const float* __restrict__ V, float* __restrict__ Vt)
{
    __shared__ float t[32][33];
    const int b = blockIdx.z;
    const int s0 = blockIdx.x * 32, d0 = blockIdx.y * 32;
    const int x = threadIdx.x, y0 = threadIdx.y;

    #pragma unroll
    for (int i = 0; i < 32; i += 8)
        t[y0 + i][x] = V[(long)b * S_LEN * DM + (long)(s0 + y0 + i) * DM + d0 + x];
    __syncthreads();
    #pragma unroll
    for (int i = 0; i < 32; i += 8)
        Vt[(long)b * DM * S_LEN + (long)(d0 + y0 + i) * S_LEN + s0 + x] = t[x][y0 + i];
}

// ---------------------------------------------------------------------------
// Fused softmax (in place) + mean over heads.
// One block per (q, b); iterates 16 heads, accumulates mean in registers.
// grid = (S_LEN, B_SZ), 256 threads x 8 elements.
// ---------------------------------------------------------------------------
__global__ __launch_bounds__(256) void softmax_mean_all(
    float* __restrict__ Sb, float* __restrict__ AW)
{
    __shared__ float red[8];
    const int b = blockIdx.y, qi = blockIdx.x, tid = threadIdx.x;

    float macc[8] = {0.f, 0.f, 0.f, 0.f, 0.f, 0.f, 0.f, 0.f};
    const float sc = 1.0f / (float)NH;

    #pragma unroll 1
    for (int h = 0; h < NH; h++) {
        float* row = Sb + ((long)((b * NH + h) * S_LEN) + qi) * S_LEN;

        float4 x0 = *reinterpret_cast<float4*>(&row[tid * 8]);
        float4 x1 = *reinterpret_cast<float4*>(&row[tid * 8 + 4]);
        float v[8] = {x0.x, x0.y, x0.z, x0.w, x1.x, x1.y, x1.z, x1.w};

        float m = v[0];
        #pragma unroll
        for (int i = 1; i < 8; i++) m = fmaxf(m, v[i]);
        #pragma unroll
        for (int o = 16; o > 0; o >>= 1) m = fmaxf(m, __shfl_xor_sync(0xffffffffu, m, o));
        if ((tid & 31) == 0) red[tid >> 5] = m;
        __syncthreads();
        m = red[0];
        #pragma unroll
        for (int i = 1; i < 8; i++) m = fmaxf(m, red[i]);
        __syncthreads();

        float s = 0.f;
        #pragma unroll
        for (int i = 0; i < 8; i++) { v[i] = __expf(v[i] - m); s += v[i]; }
        #pragma unroll
        for (int o = 16; o > 0; o >>= 1) s += __shfl_xor_sync(0xffffffffu, s, o);
        if ((tid & 31) == 0) red[tid >> 5] = s;
        __syncthreads();
        s = 0.f;
        #pragma unroll
        for (int i = 0; i < 8; i++) s += red[i];
        __syncthreads();   // red reused next head

        const float inv = 1.f / s;
        #pragma unroll
        for (int i = 0; i < 8; i++) { v[i] *= inv; macc[i] += v[i] * sc; }

        *reinterpret_cast<float4*>(&row[tid * 8])     = make_float4(v[0], v[1], v[2], v[3]);
        *reinterpret_cast<float4*>(&row[tid * 8 + 4]) = make_float4(v[4], v[5], v[6], v[7]);
    }

    float* aw = AW + ((long)b * S_LEN + qi) * S_LEN;
    *reinterpret_cast<float4*>(&aw[tid * 8])     = make_float4(macc[0], macc[1], macc[2], macc[3]);
    *reinterpret_cast<float4*>(&aw[tid * 8 + 4]) = make_float4(macc[4], macc[5], macc[6], macc[7]);
}

// ---------------------------------------------------------------------------
extern "C" void kernel_launch(void* const* d_in, const int* in_sizes, int n_in,
                              void* d_out, int out_size)
{
    const float* q  = (const float*)d_in[0];
    const float* k  = (const float*)d_in[1];
    const float* v  = (const float*)d_in[2];
    const float* Wq = (const float*)d_in[3];
    const float* Wk = (const float*)d_in[4];
    const float* Wv = (const float*)d_in[5];
    const float* Wo = (const float*)d_in[6];

    float* out  = (float*)d_out;                       // (B, S, DM)
    float* attw = out + (long)B_SZ * S_LEN * DM;       // (B, S, S)

    float *Qb, *Kb, *Vb, *Vt, *Hb, *Sb;
    cudaGetSymbolAddress((void**)&Qb, g_Q);
    cudaGetSymbolAddress((void**)&Kb, g_K);
    cudaGetSymbolAddress((void**)&Vb, g_V);
    cudaGetSymbolAddress((void**)&Vt, g_Vt);
    cudaGetSymbolAddress((void**)&Hb, g_H);
    cudaGetSymbolAddress((void**)&Sb, g_S);

    const int MS = B_SZ * S_LEN;             // 4096
    const long sBH = (long)S_LEN * DM;       // batch stride in Q/K/V/H
    const long SS  = (long)S_LEN * S_LEN;    // per (b,h) score plane

    // 1) Projections: X @ W^T  (4096 x 1024 x 1024), tensor cores
    {
        dim3 g(DM / 128, MS / 128, 1);
        mma_nt<128><<<g, 256>>>(q, Wq, Qb, DM, DM, DM, DM, 0,0, 0,0, 0,0, 1.f);
        mma_nt<128><<<g, 256>>>(k, Wk, Kb, DM, DM, DM, DM, 0,0, 0,0, 0,0, 1.f);
        mma_nt<128><<<g, 256>>>(v, Wv, Vb, DM, DM, DM, DM, 0,0, 0,0, 0,0, 1.f);
    }

    // 2) Transpose V -> Vt[b, dm, s]
    {
        dim3 g(S_LEN / 32, DM / 32, B_SZ);
        transpose_v<<<g, dim3(32, 8, 1)>>>(Vb, Vt);
    }

    // 3) Scores for ALL (b,h): z = (h<<1)|b
    {
        dim3 g(S_LEN / 128, S_LEN / 128, B_SZ * NH);
        mma_nt<128><<<g, 256>>>(Qb, Kb, Sb, DK, DM, DM, S_LEN,
                                sBH, DK, sBH, DK, NH * SS, SS, 0.125f);
    }

    // 4) Fused softmax + mean over heads
    {
        dim3 g(S_LEN, B_SZ, 1);
        softmax_mean_all<<<g, 256>>>(Sb, attw);
    }

    // 5) PV as NT: head_out[b,q,h*64+d] = sum_k P[b,h,q,k] * Vt[b,h*64+d,k]
    {
        dim3 g(1, S_LEN / 128, B_SZ * NH);
        mma_nt<64><<<g, 256>>>(Sb, Vt, Hb, S_LEN, S_LEN, S_LEN, DM,
                               NH * SS, SS,
                               (long)NH * DK * S_LEN, (long)DK * S_LEN,
                               sBH, DK, 1.f);
    }

    // 6) Output projection: H @ Wo^T
    {
        dim3 g(DM / 128, MS / 128, 1);
        mma_nt<128><<<g, 256>>>(Hb, Wo, out, DM, DM, DM, DM, 0,0, 0,0, 0,0, 1.f);
    }
}